// round 2
// baseline (speedup 1.0000x reference)
#include <cuda_runtime.h>
#include <cuda_bf16.h>

#define HDIM 16
#define UDIM 7
#define HID  64
#define XDIM (HDIM + UDIM)
#define CHUNK 512
#define NTHREADS 64

__device__ __forceinline__ unsigned smem_u32(const void* p) {
    return (unsigned)__cvta_generic_to_shared(p);
}
__device__ __forceinline__ void cp16(unsigned dst, const void* src) {
    asm volatile("cp.async.cg.shared.global [%0], [%1], 16;" :: "r"(dst), "l"(src));
}
__device__ __forceinline__ void cp4(unsigned dst, const void* src) {
    asm volatile("cp.async.ca.shared.global [%0], [%1], 4;" :: "r"(dst), "l"(src));
}
__device__ __forceinline__ void cp_commit() {
    asm volatile("cp.async.commit_group;" ::: "memory");
}
__device__ __forceinline__ void cp_wait1() {
    asm volatile("cp.async.wait_group 1;" ::: "memory");
}

// fast accurate-enough tanh: (e^{2x}-1)/(e^{2x}+1), clamped to avoid inf/inf
__device__ __forceinline__ float ftanh(float x) {
    x = fminf(fmaxf(x, -15.0f), 15.0f);
    float e = __expf(2.0f * x);
    return __fdividef(e - 1.0f, e + 1.0f);
}

__global__ void __launch_bounds__(NTHREADS, 1) node_scan_kernel(
    const float* __restrict__ U,
    const float* __restrict__ W1, const float* __restrict__ b1,
    const float* __restrict__ W2, const float* __restrict__ b2,
    const float* __restrict__ W3, const float* __restrict__ b3,
    const float* __restrict__ wd, const float* __restrict__ bd,
    const float* __restrict__ wt, const float* __restrict__ bt,
    const float* __restrict__ wc, const float* __restrict__ bc,
    const float* __restrict__ h0,
    float* __restrict__ out, int T)
{
    __shared__ __align__(16) float ubuf[2][CHUNK * UDIM];
    __shared__ __align__(16) float hs[HDIM];
    __shared__ __align__(16) float z1s[HID];
    __shared__ __align__(16) float z2s[HID];

    const int tid = threadIdx.x;
    const float dt = 5.0f / 60.0f;

    // ---- load weights into registers ----
    float w1[XDIM];
    #pragma unroll
    for (int k = 0; k < XDIM; k++) w1[k] = W1[tid * XDIM + k];
    const float b1r = b1[tid];

    float w2[HID];
    #pragma unroll
    for (int k = 0; k < HID; k++) w2[k] = W2[tid * HID + k];
    const float b2r = b2[tid];

    float w3[HID];
    float b3r = 0.0f;
    if (tid < HDIM) {
        #pragma unroll
        for (int k = 0; k < HID; k++) w3[k] = W3[tid * HID + k];
        b3r = b3[tid];
    }

    // readout lanes: tid 32 -> delay, 33 -> taxi, 34 -> loglam (warp 1 lanes 0..2)
    float wr[HDIM];
    float br = 0.0f;
    float* outp = nullptr;
    if (tid == 32) {
        #pragma unroll
        for (int k = 0; k < HDIM; k++) wr[k] = wd[k];
        br = bd[0]; outp = out;
    } else if (tid == 33) {
        #pragma unroll
        for (int k = 0; k < HDIM; k++) wr[k] = wt[k];
        br = bt[0]; outp = out + T;
    } else if (tid == 34) {
        #pragma unroll
        for (int k = 0; k < HDIM; k++) wr[k] = wc[k];
        br = bc[0]; outp = out + 2 * T;
    } else {
        #pragma unroll
        for (int k = 0; k < HDIM; k++) wr[k] = 0.0f;
    }

    if (tid < HDIM) hs[tid] = h0[tid];

    const int n_chunks = (T + CHUNK - 1) / CHUNK;

    // chunk copy: 16B cp.async; every chunk start offset is 16B aligned
    // (CHUNK*UDIM*4 = 14336 bytes, multiple of 16)
    auto copy_chunk = [&](int cc) {
        if (cc >= n_chunks) return;
        const int t0 = cc * CHUNK;
        const int nf = min(CHUNK, T - t0) * UDIM;
        const float* src = U + t0 * UDIM;
        float* dst = ubuf[cc & 1];
        const int nv = nf >> 2;
        for (int idx = tid; idx < nv; idx += NTHREADS)
            cp16(smem_u32(dst + 4 * idx), src + 4 * idx);
        for (int idx = (nv << 2) + tid; idx < nf; idx += NTHREADS)
            cp4(smem_u32(dst + idx), src + idx);
    };

    copy_chunk(0); cp_commit();
    copy_chunk(1); cp_commit();

    for (int c = 0; c < n_chunks; c++) {
        cp_wait1();
        __syncthreads();   // chunk data visible; hs valid
        const int nst = min(CHUNK, T - c * CHUNK);
        const float* ub = ubuf[c & 1];

        for (int k = 0; k < nst; k++) {
            const int t = c * CHUNK + k;

            // ---- phase A: layer 1 (all 64 threads). Capture h_t in registers. ----
            float h[HDIM];
            {
                const float4* h4 = (const float4*)hs;
                float4 ha = h4[0], hb = h4[1], hc = h4[2], hd = h4[3];
                h[0] = ha.x;  h[1] = ha.y;  h[2] = ha.z;  h[3] = ha.w;
                h[4] = hb.x;  h[5] = hb.y;  h[6] = hb.z;  h[7] = hb.w;
                h[8] = hc.x;  h[9] = hc.y;  h[10] = hc.z; h[11] = hc.w;
                h[12] = hd.x; h[13] = hd.y; h[14] = hd.z; h[15] = hd.w;
            }
            float a0 = b1r, a1 = 0.0f, a2 = 0.0f, a3 = 0.0f;
            #pragma unroll
            for (int j = 0; j < HDIM; j += 4) {
                a0 = fmaf(w1[j + 0], h[j + 0], a0);
                a1 = fmaf(w1[j + 1], h[j + 1], a1);
                a2 = fmaf(w1[j + 2], h[j + 2], a2);
                a3 = fmaf(w1[j + 3], h[j + 3], a3);
            }
            {
                const float* up = ub + k * UDIM;
                float u0 = up[0], u1 = up[1], u2 = up[2], u3 = up[3];
                float u4 = up[4], u5 = up[5], u6 = up[6];
                a0 = fmaf(w1[16], u0, a0);
                a1 = fmaf(w1[17], u1, a1);
                a2 = fmaf(w1[18], u2, a2);
                a3 = fmaf(w1[19], u3, a3);
                a0 = fmaf(w1[20], u4, a0);
                a1 = fmaf(w1[21], u5, a1);
                a2 = fmaf(w1[22], u6, a2);
            }
            z1s[tid] = ftanh((a0 + a1) + (a2 + a3));
            __syncthreads();

            // ---- phase B: layer 2 (all 64 threads) ----
            float c0 = b2r, c1 = 0.0f, c2 = 0.0f, c3 = 0.0f;
            {
                const float4* z14 = (const float4*)z1s;
                #pragma unroll
                for (int j = 0; j < HID / 4; j++) {
                    float4 v = z14[j];
                    c0 = fmaf(w2[4 * j + 0], v.x, c0);
                    c1 = fmaf(w2[4 * j + 1], v.y, c1);
                    c2 = fmaf(w2[4 * j + 2], v.z, c2);
                    c3 = fmaf(w2[4 * j + 3], v.w, c3);
                }
            }
            z2s[tid] = ftanh((c0 + c1) + (c2 + c3));
            __syncthreads();

            // ---- phase C: layer 3 + h update (threads 0..15), readouts (32..34) ----
            if (tid < HDIM) {
                float d0 = b3r, d1 = 0.0f, d2 = 0.0f, d3 = 0.0f;
                const float4* z24 = (const float4*)z2s;
                #pragma unroll
                for (int j = 0; j < HID / 4; j++) {
                    float4 v = z24[j];
                    d0 = fmaf(w3[4 * j + 0], v.x, d0);
                    d1 = fmaf(w3[4 * j + 1], v.y, d1);
                    d2 = fmaf(w3[4 * j + 2], v.z, d2);
                    d3 = fmaf(w3[4 * j + 3], v.w, d3);
                }
                float dh = (d0 + d1) + (d2 + d3);
                hs[tid] = hs[tid] + dh * dt;   // h_{t+1}
            } else if (tid >= 32 && tid < 35) {
                // readout on pre-update h (captured in phase A)
                float r = br;
                #pragma unroll
                for (int j = 0; j < HDIM; j++) r = fmaf(wr[j], h[j], r);
                outp[t] = r;
            }
            __syncthreads();
        }

        // prefetch chunk c+2 into the buffer we just finished reading
        copy_chunk(c + 2);
        cp_commit();
    }

    __syncthreads();
    if (tid < HDIM) out[3 * T + tid] = hs[tid];
}

extern "C" void kernel_launch(void* const* d_in, const int* in_sizes, int n_in,
                              void* d_out, int out_size)
{
    const int T = in_sizes[0] / UDIM;
    node_scan_kernel<<<1, NTHREADS>>>(
        (const float*)d_in[0],                      // U
        (const float*)d_in[1], (const float*)d_in[2],   // W1, b1
        (const float*)d_in[3], (const float*)d_in[4],   // W2, b2
        (const float*)d_in[5], (const float*)d_in[6],   // W3, b3
        (const float*)d_in[7], (const float*)d_in[8],   // wd, bd
        (const float*)d_in[9], (const float*)d_in[10],  // wt, bt
        (const float*)d_in[11], (const float*)d_in[12], // wc, bc
        (const float*)d_in[13],                     // h0
        (float*)d_out, T);
}